// round 13
// baseline (speedup 1.0000x reference)
#include <cuda_runtime.h>
#include <cuda_bf16.h>
#include <math.h>
#include <stdint.h>

#define NN 512
#define CS 1024
#define CZd 128
#define Hh 12
#define HDd 16
#define PQp 4
#define PVp 8
#define NPROJ 1152   // 192 q | 384 kv | 144 qp | 432 kvp
#define KCAT 2112

// ---------------- scratch (device globals; no allocation allowed) ----------
__device__ __align__(16) float g_bias[NPROJ];
__device__ __align__(16) float g_proj[NN * NPROJ];
__device__ __align__(16) float g_qpts[NN * Hh * PQp * 3];
__device__ __align__(16) float g_kpts[NN * Hh * PQp * 3];
__device__ __align__(16) float g_a[Hh * NN * NN];           // bz output (logit bias)
__device__ __align__(16) float g_o1[Hh * NN * 64];          // attn out [h][i][64]

// bf16 split operands for tensor-core GEMMs
__device__ __align__(16) __nv_bfloat16 g_sh[NN * CS];
__device__ __align__(16) __nv_bfloat16 g_sl[NN * CS];
__device__ __align__(16) __nv_bfloat16 g_Wth[NPROJ * CS];   // W^T [n][k] K-major
__device__ __align__(16) __nv_bfloat16 g_Wtl[NPROJ * CS];
__device__ __align__(16) __nv_bfloat16 g_WoTh[1024 * KCAT]; // Wout^T [n][k]
__device__ __align__(16) __nv_bfloat16 g_WoTl[1024 * KCAT];
__device__ __align__(16) __nv_bfloat16 g_cath[NN * KCAT];
__device__ __align__(16) __nv_bfloat16 g_catl[NN * KCAT];
__device__ __align__(16) __nv_bfloat16 g_ah[Hh * NN * NN];  // attn weights hi
__device__ __align__(16) __nv_bfloat16 g_al[Hh * NN * NN];  // attn weights lo
__device__ __align__(16) __nv_bfloat16 g_vTh[Hh * 64 * NN]; // vcat^T [h][c][j] (pad 64)
__device__ __align__(16) __nv_bfloat16 g_vTl[Hh * 64 * NN];

// ---------------- warp-level bf16 MMA + ldmatrix (baseline PTX) -------------
__device__ __forceinline__ void mma16816(float* c, const uint32_t* a, const uint32_t* b) {
    asm volatile(
        "mma.sync.aligned.m16n8k16.row.col.f32.bf16.bf16.f32 "
        "{%0,%1,%2,%3}, {%4,%5,%6,%7}, {%8,%9}, {%0,%1,%2,%3};"
        : "+f"(c[0]), "+f"(c[1]), "+f"(c[2]), "+f"(c[3])
        : "r"(a[0]), "r"(a[1]), "r"(a[2]), "r"(a[3]), "r"(b[0]), "r"(b[1]));
}
__device__ __forceinline__ void ldmx4(uint32_t* r, uint32_t addr) {
    asm volatile("ldmatrix.sync.aligned.m8n8.x4.shared.b16 {%0,%1,%2,%3}, [%4];"
                 : "=r"(r[0]), "=r"(r[1]), "=r"(r[2]), "=r"(r[3]) : "r"(addr));
}
__device__ __forceinline__ void ldmx2(uint32_t* r, uint32_t addr) {
    asm volatile("ldmatrix.sync.aligned.m8n8.x2.shared.b16 {%0,%1}, [%2];"
                 : "=r"(r[0]), "=r"(r[1]) : "r"(addr));
}
__device__ __forceinline__ uint32_t smem_u32(const void* p) {
    uint32_t a;
    asm("{ .reg .u64 t; cvta.to.shared.u64 t, %1; cvt.u32.u64 %0, t; }" : "=r"(a) : "l"(p));
    return a;
}
__device__ __forceinline__ void split_store(float v, __nv_bfloat16* dh, __nv_bfloat16* dl) {
    __nv_bfloat16 hi = __float2bfloat16(v);
    *dh = hi;
    *dl = __float2bfloat16(v - __bfloat162float(hi));
}

// ---------------- hgemm: C = A @ B^T, split-bf16, HMMA, z-batched -----------
// A: [M][K] bf16 hi/lo (K contiguous). B: [Nw][K] bf16 hi/lo (K contiguous).
// C fp32 [M][Nw] (+bias). M%64==0, Nw%64==0, K%32==0.
// grid (Nw/64, M/64, batch), block 256 (8 warps: 4 m-bands x 2 n-bands).
// zA/zB strides in u32 words; zC in floats.
template <bool HAS_BIAS>
__global__ __launch_bounds__(256)
void hgemm(const __nv_bfloat16* __restrict__ Ah_, const __nv_bfloat16* __restrict__ Al_,
           const __nv_bfloat16* __restrict__ Bh_, const __nv_bfloat16* __restrict__ Bl_,
           const float* __restrict__ bias, float* __restrict__ C,
           int M, int K, int Nw, long zA, long zB, long zC) {
    __shared__ __align__(16) uint32_t sm[2][4][64 * 20];

    const int t = threadIdx.x;
    const int wid = t >> 5, lane = t & 31;
    const int wm = wid >> 1, wn = wid & 1;
    const int lr = lane >> 2, lc = lane & 3;
    const int m0 = blockIdx.y * 64, n0 = blockIdx.x * 64;
    const int K2 = K >> 1;
    const int NC = K2 >> 4;

    const uint32_t* Ah32 = (const uint32_t*)Ah_ + blockIdx.z * zA;
    const uint32_t* Al32 = (const uint32_t*)Al_ + blockIdx.z * zA;
    const uint32_t* Bh32 = (const uint32_t*)Bh_ + blockIdx.z * zB;
    const uint32_t* Bl32 = (const uint32_t*)Bl_ + blockIdx.z * zB;
    C += blockIdx.z * zC;

    const int grow = t >> 2, gw = (t & 3) * 4;
    const long aBase = (long)(m0 + grow) * K2 + gw;
    const long bBase = (long)(n0 + grow) * K2 + gw;
    const int sIdx = grow * 20 + gw;

    const uint32_t smb = smem_u32(sm);
    const int aRowOff = (16 * wm + (lane & 15)) * 20 + ((lane >> 4) << 2);
    const int bRowOff0 = (32 * wn + (lane & 7)) * 20 + (((lane >> 3) & 1) << 2);

    float acc[4][4];
#pragma unroll
    for (int j = 0; j < 4; j++)
#pragma unroll
        for (int r = 0; r < 4; r++) acc[j][r] = 0.f;

    uint4 rAh = *(const uint4*)(Ah32 + aBase);
    uint4 rAl = *(const uint4*)(Al32 + aBase);
    uint4 rBh = *(const uint4*)(Bh32 + bBase);
    uint4 rBl = *(const uint4*)(Bl32 + bBase);
    *(uint4*)&sm[0][0][sIdx] = rAh;
    *(uint4*)&sm[0][1][sIdx] = rAl;
    *(uint4*)&sm[0][2][sIdx] = rBh;
    *(uint4*)&sm[0][3][sIdx] = rBl;
    __syncthreads();

    for (int c = 0; c < NC; c++) {
        const int cur = c & 1;
        if (c + 1 < NC) {
            const long off = (long)(c + 1) * 16;
            rAh = *(const uint4*)(Ah32 + aBase + off);
            rAl = *(const uint4*)(Al32 + aBase + off);
            rBh = *(const uint4*)(Bh32 + bBase + off);
            rBl = *(const uint4*)(Bl32 + bBase + off);
        }

        const uint32_t baseAh = smb + ((cur * 4 + 0) * 1280) * 4;
        const uint32_t baseAl = smb + ((cur * 4 + 1) * 1280) * 4;
        const uint32_t baseBh = smb + ((cur * 4 + 2) * 1280) * 4;
        const uint32_t baseBl = smb + ((cur * 4 + 3) * 1280) * 4;

#pragma unroll
        for (int ks = 0; ks < 2; ks++) {
            const int kb = ks * 8;
            uint32_t ah[4], al[4];
            ldmx4(ah, baseAh + (aRowOff + kb) * 4);
            ldmx4(al, baseAl + (aRowOff + kb) * 4);
#pragma unroll
            for (int j = 0; j < 4; j++) {
                uint32_t bh[2], bl[2];
                const uint32_t bo = (bRowOff0 + j * 8 * 20 + kb) * 4;
                ldmx2(bh, baseBh + bo);
                ldmx2(bl, baseBl + bo);
                mma16816(acc[j], ah, bh);
                mma16816(acc[j], ah, bl);
                mma16816(acc[j], al, bh);
            }
        }

        if (c + 1 < NC) {
            const int nxt = cur ^ 1;
            *(uint4*)&sm[nxt][0][sIdx] = rAh;
            *(uint4*)&sm[nxt][1][sIdx] = rAl;
            *(uint4*)&sm[nxt][2][sIdx] = rBh;
            *(uint4*)&sm[nxt][3][sIdx] = rBl;
            __syncthreads();
        }
    }

    const int mrow = m0 + 16 * wm + lr;
#pragma unroll
    for (int j = 0; j < 4; j++) {
        const int n = n0 + 32 * wn + 8 * j + lc * 2;
        float b0 = HAS_BIAS ? bias[n] : 0.f;
        float b1 = HAS_BIAS ? bias[n + 1] : 0.f;
        C[(long)mrow * Nw + n] = acc[j][0] + b0;
        C[(long)mrow * Nw + n + 1] = acc[j][1] + b1;
        C[(long)(mrow + 8) * Nw + n] = acc[j][2] + b0;
        C[(long)(mrow + 8) * Nw + n + 1] = acc[j][3] + b1;
    }
}

// ---------------- conversions / transposes ----------------------------------
__global__ void conv_hl_kernel(const float* __restrict__ src, __nv_bfloat16* __restrict__ dh,
                               __nv_bfloat16* __restrict__ dl, int n) {
    int idx = blockIdx.x * 256 + threadIdx.x;
    if (idx < n) split_store(src[idx], dh + idx, dl + idx);
}

__global__ void packWT_kernel(const float* __restrict__ Wq, const float* __restrict__ Wkv,
                              const float* __restrict__ Wqp, const float* __restrict__ Wkvp) {
    __shared__ float sm[32][33];
    const int c0 = blockIdx.x * 32, k0 = blockIdx.y * 32;
    const int tx = threadIdx.x, ty = threadIdx.y;
#pragma unroll
    for (int rr = 0; rr < 4; rr++) {
        int k = k0 + ty + rr * 8;
        int c = c0 + tx;
        float v;
        if (c < 192) v = Wq[k * 192 + c];
        else if (c < 576) v = Wkv[k * 384 + (c - 192)];
        else if (c < 720) v = Wqp[k * 144 + (c - 576)];
        else v = Wkvp[k * 432 + (c - 720)];
        sm[ty + rr * 8][tx] = v;
    }
    __syncthreads();
#pragma unroll
    for (int rr = 0; rr < 4; rr++) {
        int c = c0 + ty + rr * 8;
        int k = k0 + tx;
        float v = sm[tx][ty + rr * 8];
        split_store(v, &g_Wth[(long)c * CS + k], &g_Wtl[(long)c * CS + k]);
    }
}

__global__ void WoutT_kernel(const float* __restrict__ Wout) {
    __shared__ float sm[32][33];
    const int n0 = blockIdx.x * 32, k0 = blockIdx.y * 32;
    const int tx = threadIdx.x, ty = threadIdx.y;
#pragma unroll
    for (int rr = 0; rr < 4; rr++)
        sm[ty + rr * 8][tx] = Wout[(long)(k0 + ty + rr * 8) * 1024 + n0 + tx];
    __syncthreads();
#pragma unroll
    for (int rr = 0; rr < 4; rr++) {
        int n = n0 + ty + rr * 8;
        int k = k0 + tx;
        float v = sm[tx][ty + rr * 8];
        split_store(v, &g_WoTh[(long)n * KCAT + k], &g_WoTl[(long)n * KCAT + k]);
    }
}

__global__ void packbias_kernel(const float* __restrict__ bq, const float* __restrict__ bkv,
                                const float* __restrict__ bqp, const float* __restrict__ bkvp) {
    int c = blockIdx.x * 256 + threadIdx.x;
    if (c < NPROJ) {
        float v;
        if (c < 192) v = bq[c];
        else if (c < 576) v = bkv[c - 192];
        else if (c < 720) v = bqp[c - 576];
        else v = bkvp[c - 720];
        g_bias[c] = v;
    }
}

// ---------------- point transform + vcatT (split-bf16) ----------------------
__global__ void pts_kernel(const float* __restrict__ rot, const float* __restrict__ trans) {
    const int i = blockIdx.x;
    const int t = threadIdx.x; // 384
    __shared__ float R[9], T[3];
    if (t < 9) R[t] = rot[i * 9 + t];
    if (t < 3) T[t] = trans[i * 3 + t];
    __syncthreads();

    const float* P = g_proj + (long)i * NPROJ;

    if (t < 48) {
        float l0 = P[576 + 0 * 48 + t];
        float l1 = P[576 + 1 * 48 + t];
        float l2 = P[576 + 2 * 48 + t];
#pragma unroll
        for (int ci = 0; ci < 3; ci++)
            g_qpts[i * 144 + 3 * t + ci] =
                R[ci * 3 + 0] * l0 + R[ci * 3 + 1] * l1 + R[ci * 3 + 2] * l2 + T[ci];
    } else if (t < 96) {
        int u = t - 48;
        int h = u >> 2, p = u & 3;
        int pidx = h * 12 + p;
        float l0 = P[720 + 0 * 144 + pidx];
        float l1 = P[720 + 1 * 144 + pidx];
        float l2 = P[720 + 2 * 144 + pidx];
#pragma unroll
        for (int ci = 0; ci < 3; ci++)
            g_kpts[i * 144 + 3 * u + ci] =
                R[ci * 3 + 0] * l0 + R[ci * 3 + 1] * l1 + R[ci * 3 + 2] * l2 + T[ci];
    } else if (t < 192) {
        int u = t - 96;           // h*8+p
        int h = u >> 3, p = u & 7;
        int pidx = h * 12 + 4 + p;
        float l0 = P[720 + 0 * 144 + pidx];
        float l1 = P[720 + 1 * 144 + pidx];
        float l2 = P[720 + 2 * 144 + pidx];
#pragma unroll
        for (int ci = 0; ci < 3; ci++) {
            float w = R[ci * 3 + 0] * l0 + R[ci * 3 + 1] * l1 + R[ci * 3 + 2] * l2 + T[ci];
            long idx = ((long)h * 64 + 16 + p * 3 + ci) * NN + i;
            split_store(w, &g_vTh[idx], &g_vTl[idx]);
        }
    } else {
        int u = t - 192;          // h*16+d
        int h = u >> 4, d = u & 15;
        long idx = ((long)h * 64 + d) * NN + i;
        split_store(P[192 + h * 32 + 16 + d], &g_vTh[idx], &g_vTl[idx]);
    }
    // zero pad cols 40..63
    if (t < 288) {
        int h = t / 24, c = 40 + t % 24;
        long idx = ((long)h * 64 + c) * NN + i;
        g_vTh[idx] = __float2bfloat16(0.f);
        g_vTl[idx] = __float2bfloat16(0.f);
    }
}

// ---------------- b = sqrt(1/3) * (z @ Wb + bb) -> g_a ----------------------
__global__ __launch_bounds__(256)
void bz_kernel(const float* __restrict__ z, const float* __restrict__ Wb,
               const float* __restrict__ bb) {
    __shared__ float4 ws4[Hh][32];
    __shared__ float bbs[Hh];
    __shared__ __align__(16) float zs[512][20];

    const int i = blockIdx.x;
    const int t = threadIdx.x;

    for (int idx = t; idx < Hh * 32; idx += 256) {
        int h = idx >> 5, c4 = idx & 31;
        ws4[h][c4] = make_float4(Wb[(c4 * 4 + 0) * Hh + h], Wb[(c4 * 4 + 1) * Hh + h],
                                 Wb[(c4 * 4 + 2) * Hh + h], Wb[(c4 * 4 + 3) * Hh + h]);
    }
    if (t < Hh) bbs[t] = bb[t];

    float acc0[Hh], acc1[Hh];
#pragma unroll
    for (int h = 0; h < Hh; h++) { acc0[h] = 0.f; acc1[h] = 0.f; }

    for (int c0 = 0; c0 < 128; c0 += 16) {
        __syncthreads();
        for (int idx = t; idx < 2048; idx += 256) {
            int r = idx >> 2, c4 = idx & 3;
            *(float4*)&zs[r][c4 * 4] =
                *(const float4*)&z[((long)i * 512 + r) * 128 + c0 + c4 * 4];
        }
        __syncthreads();

        const int wb = c0 >> 2;
#pragma unroll
        for (int c4 = 0; c4 < 4; c4++) {
            float4 za = *(const float4*)&zs[t][c4 * 4];
            float4 zb = *(const float4*)&zs[t + 256][c4 * 4];
#pragma unroll
            for (int h = 0; h < Hh; h++) {
                float4 w = ws4[h][wb + c4];
                acc0[h] += za.x * w.x + za.y * w.y + za.z * w.z + za.w * w.w;
                acc1[h] += zb.x * w.x + zb.y * w.y + zb.z * w.z + zb.w * w.w;
            }
        }
    }

    const float k13 = 0.57735026918962576f;
#pragma unroll
    for (int h = 0; h < Hh; h++) {
        g_a[(((long)h << 9) + i) * 512 + t] = k13 * (acc0[h] + bbs[h]);
        g_a[(((long)h << 9) + i) * 512 + t + 256] = k13 * (acc1[h] + bbs[h]);
    }
}

// ---------------- fused logits + softmax -> split-bf16 a --------------------
// block (h, 8 i-rows), warp ti owns row. q-side in registers; k-side in one
// merged smem row [36]: 16 k | 12 kp | mask. float4 reads, conflict-free.
__global__ __launch_bounds__(256)
void logits_softmax_kernel(const float* __restrict__ mask, const float* __restrict__ head_w) {
    const int h = blockIdx.y;
    const int i0 = blockIdx.x * 8;
    const int t = threadIdx.x;
    const int ti = t >> 5;
    const int lane = t & 31;

    __shared__ __align__(16) float krow[256][36];

    const int irow = i0 + ti;
    const float4 q0 = *(const float4*)&g_proj[(long)irow * NPROJ + h * 16];
    const float4 q1 = *(const float4*)&g_proj[(long)irow * NPROJ + h * 16 + 4];
    const float4 q2 = *(const float4*)&g_proj[(long)irow * NPROJ + h * 16 + 8];
    const float4 q3 = *(const float4*)&g_proj[(long)irow * NPROJ + h * 16 + 12];
    const float4 p0 = *(const float4*)&g_qpts[irow * 144 + h * 12];
    const float4 p1 = *(const float4*)&g_qpts[irow * 144 + h * 12 + 4];
    const float4 p2 = *(const float4*)&g_qpts[irow * 144 + h * 12 + 8];
    const float mi = mask[irow];

    float x = head_w[h];
    float sp = (x > 20.f) ? x : log1pf(__expf(x));
    const float hw = sp * 0.13608276348795434f;   // sqrt(1/54)
    const float kqk = 0.14433756729740643f;       // sqrt(1/48)

    float v[16];
    const long rowBase = (((long)h << 9) + irow) * 512;

    for (int jc = 0; jc < 2; jc++) {
        const int jbase = jc * 256;
        __syncthreads();
        for (int idx = t; idx < 256 * 16; idx += 256) {
            int r = idx >> 4, d = idx & 15;
            krow[r][d] = g_proj[(long)(jbase + r) * NPROJ + 192 + h * 32 + d];
        }
        for (int idx = t; idx < 256 * 12; idx += 256) {
            int r = idx / 12, d = idx % 12;
            krow[r][16 + d] = g_kpts[(jbase + r) * 144 + h * 12 + d];
        }
        if (t < 256) krow[t][28] = mask[jbase + t];
        __syncthreads();

#pragma unroll
        for (int q = 0; q < 8; q++) {
            const int r = lane + q * 32;
            const float4 k0 = *(const float4*)&krow[r][0];
            const float4 k1 = *(const float4*)&krow[r][4];
            const float4 k2 = *(const float4*)&krow[r][8];
            const float4 k3 = *(const float4*)&krow[r][12];
            const float4 kp0 = *(const float4*)&krow[r][16];
            const float4 kp1 = *(const float4*)&krow[r][20];
            const float4 kp2 = *(const float4*)&krow[r][24];
            const float mj = krow[r][28];

            float dot = q0.x * k0.x + q0.y * k0.y + q0.z * k0.z + q0.w * k0.w
                      + q1.x * k1.x + q1.y * k1.y + q1.z * k1.z + q1.w * k1.w
                      + q2.x * k2.x + q2.y * k2.y + q2.z * k2.z + q2.w * k2.w
                      + q3.x * k3.x + q3.y * k3.y + q3.z * k3.z + q3.w * k3.w;
            float d0 = p0.x - kp0.x, d1 = p0.y - kp0.y, d2 = p0.z - kp0.z, d3 = p0.w - kp0.w;
            float d4 = p1.x - kp1.x, d5 = p1.y - kp1.y, d6 = p1.z - kp1.z, d7 = p1.w - kp1.w;
            float d8 = p2.x - kp2.x, d9 = p2.y - kp2.y, da = p2.z - kp2.z, db = p2.w - kp2.w;
            float pt = d0 * d0 + d1 * d1 + d2 * d2 + d3 * d3 + d4 * d4 + d5 * d5
                     + d6 * d6 + d7 * d7 + d8 * d8 + d9 * d9 + da * da + db * db;
            float b = g_a[rowBase + jbase + r];
            v[jc * 8 + q] = dot * kqk + b - 0.5f * hw * pt
                          + 100000.0f * (mi * mj - 1.0f);
        }
    }

    float m = v[0];
#pragma unroll
    for (int q = 1; q < 16; q++) m = fmaxf(m, v[q]);
#pragma unroll
    for (int o = 16; o; o >>= 1) m = fmaxf(m, __shfl_xor_sync(0xffffffffu, m, o));

    float s = 0.f;
#pragma unroll
    for (int q = 0; q < 16; q++) { v[q] = __expf(v[q] - m); s += v[q]; }
#pragma unroll
    for (int o = 16; o; o >>= 1) s += __shfl_xor_sync(0xffffffffu, s, o);
    const float inv = 1.f / s;

#pragma unroll
    for (int q = 0; q < 16; q++) {
        int j = (q >> 3) * 256 + (q & 7) * 32 + lane;
        split_store(v[q] * inv, &g_ah[rowBase + j], &g_al[rowBase + j]);
    }
}

// ---------------- o_pair -> cat (bf16 hi/lo direct) -------------------------
__global__ __launch_bounds__(256)
void opair_kernel(const float* __restrict__ z) {
    const int i = blockIdx.x;
    __shared__ __align__(16) float sa[12][512];
    __shared__ __align__(16) float zs[32][128];
    const int t = threadIdx.x; // 256

    for (int idx = t; idx < 12 * 256; idx += 256) {
        int h = idx >> 8, j2 = idx & 255;
        long base = (((long)h << 9) + i) * 512 + j2 * 2;
        float h0 = __bfloat162float(g_ah[base]) + __bfloat162float(g_al[base]);
        float h1 = __bfloat162float(g_ah[base + 1]) + __bfloat162float(g_al[base + 1]);
        sa[h][j2 * 2] = h0;
        sa[h][j2 * 2 + 1] = h1;
    }

    const int c = t & 127;
    const int hh = t >> 7;
    float acc[6] = {0.f, 0.f, 0.f, 0.f, 0.f, 0.f};

    for (int j0 = 0; j0 < 512; j0 += 32) {
        __syncthreads();
        for (int idx = t; idx < 32 * 32; idx += 256) {
            int r = idx >> 5, c4 = idx & 31;
            ((float4*)&zs[r][0])[c4] =
                ((const float4*)&z[(((long)i << 9) + j0 + r) * 128])[c4];
        }
        __syncthreads();
#pragma unroll
        for (int r4 = 0; r4 < 8; r4++) {
            float z0 = zs[r4 * 4 + 0][c];
            float z1 = zs[r4 * 4 + 1][c];
            float z2 = zs[r4 * 4 + 2][c];
            float z3 = zs[r4 * 4 + 3][c];
#pragma unroll
            for (int q = 0; q < 6; q++) {
                float4 s4 = *(const float4*)&sa[hh * 6 + q][j0 + r4 * 4];
                acc[q] += s4.x * z0 + s4.y * z1 + s4.z * z2 + s4.w * z3;
            }
        }
    }
#pragma unroll
    for (int q = 0; q < 6; q++) {
        long idx = (long)i * KCAT + 576 + (hh * 6 + q) * 128 + c;
        split_store(acc[q], &g_cath[idx], &g_catl[idx]);
    }
}

// ---------------- assemble: o copy + inverse-frame o_pt + norms (bf16) ------
__global__ void assemble_kernel(const float* __restrict__ rot, const float* __restrict__ trans) {
    const int i = blockIdx.x;
    const int t = threadIdx.x; // 192
    __shared__ float R[9], T[3];
    if (t < 9) R[t] = rot[i * 9 + t];
    if (t < 3) T[t] = trans[i * 3 + t];
    __syncthreads();

    {
        int h = t >> 4, d = t & 15;
        long idx = (long)i * KCAT + t;
        split_store(g_o1[(((long)h << 9) + i) * 64 + d], &g_cath[idx], &g_catl[idx]);
    }
    if (t < 96) {
        int h = t >> 3, p = t & 7;
        const float* src = &g_o1[(((long)h << 9) + i) * 64 + 16 + p * 3];
        float w0 = src[0] - T[0];
        float w1 = src[1] - T[1];
        float w2 = src[2] - T[2];
        float l0 = R[0] * w0 + R[3] * w1 + R[6] * w2;
        float l1 = R[1] * w0 + R[4] * w1 + R[7] * w2;
        float l2 = R[2] * w0 + R[5] * w1 + R[8] * w2;
        long b = (long)i * KCAT;
        split_store(l0, &g_cath[b + 192 + t], &g_catl[b + 192 + t]);
        split_store(l1, &g_cath[b + 288 + t], &g_catl[b + 288 + t]);
        split_store(l2, &g_cath[b + 384 + t], &g_catl[b + 384 + t]);
        float nrm = sqrtf(l0 * l0 + l1 * l1 + l2 * l2 + 1e-8f);
        split_store(nrm, &g_cath[b + 480 + t], &g_catl[b + 480 + t]);
    }
}

// ---------------- stream/event state (lazy init, host-side only) ------------
static cudaStream_t g_s1 = nullptr, g_s2 = nullptr;
static cudaEvent_t g_evRoot, g_evBz, g_evWo, g_evLS, g_evOp, g_evPrep;

// ---------------- launch ----------------------------------------------------
extern "C" void kernel_launch(void* const* d_in, const int* in_sizes, int n_in,
                              void* d_out, int out_size) {
    const float* s     = (const float*)d_in[0];
    const float* z     = (const float*)d_in[1];
    const float* rot   = (const float*)d_in[2];
    const float* trans = (const float*)d_in[3];
    const float* mask  = (const float*)d_in[4];
    const float* Wq    = (const float*)d_in[5];
    const float* bq    = (const float*)d_in[6];
    const float* Wkv   = (const float*)d_in[7];
    const float* bkv   = (const float*)d_in[8];
    const float* Wqp   = (const float*)d_in[9];
    const float* bqp   = (const float*)d_in[10];
    const float* Wkvp  = (const float*)d_in[11];
    const float* bkvp  = (const float*)d_in[12];
    const float* Wb    = (const float*)d_in[13];
    const float* bb    = (const float*)d_in[14];
    const float* head_w= (const float*)d_in[15];
    const float* Wout  = (const float*)d_in[16];
    const float* bout  = (const float*)d_in[17];
    float* out = (float*)d_out;

    if (!g_s1) {
        cudaStreamCreateWithFlags(&g_s1, cudaStreamNonBlocking);
        cudaStreamCreateWithFlags(&g_s2, cudaStreamNonBlocking);
        cudaEventCreateWithFlags(&g_evRoot, cudaEventDisableTiming);
        cudaEventCreateWithFlags(&g_evBz, cudaEventDisableTiming);
        cudaEventCreateWithFlags(&g_evWo, cudaEventDisableTiming);
        cudaEventCreateWithFlags(&g_evLS, cudaEventDisableTiming);
        cudaEventCreateWithFlags(&g_evOp, cudaEventDisableTiming);
        cudaEventCreateWithFlags(&g_evPrep, cudaEventDisableTiming);
    }

    float *pBias, *pProj, *pO1;
    __nv_bfloat16 *pSh, *pSl, *pWth, *pWtl, *pWoTh, *pWoTl, *pCath, *pCatl;
    __nv_bfloat16 *pAh, *pAl, *pVTh, *pVTl;
    cudaGetSymbolAddress((void**)&pBias, g_bias);
    cudaGetSymbolAddress((void**)&pProj, g_proj);
    cudaGetSymbolAddress((void**)&pO1, g_o1);
    cudaGetSymbolAddress((void**)&pSh, g_sh);
    cudaGetSymbolAddress((void**)&pSl, g_sl);
    cudaGetSymbolAddress((void**)&pWth, g_Wth);
    cudaGetSymbolAddress((void**)&pWtl, g_Wtl);
    cudaGetSymbolAddress((void**)&pWoTh, g_WoTh);
    cudaGetSymbolAddress((void**)&pWoTl, g_WoTl);
    cudaGetSymbolAddress((void**)&pCath, g_cath);
    cudaGetSymbolAddress((void**)&pCatl, g_catl);
    cudaGetSymbolAddress((void**)&pAh, g_ah);
    cudaGetSymbolAddress((void**)&pAl, g_al);
    cudaGetSymbolAddress((void**)&pVTh, g_vTh);
    cudaGetSymbolAddress((void**)&pVTl, g_vTl);

    // fork side streams off the capture (root) stream
    cudaEventRecord(g_evRoot, 0);
    cudaStreamWaitEvent(g_s1, g_evRoot, 0);
    cudaStreamWaitEvent(g_s2, g_evRoot, 0);

    // s1: z-bound bz (independent of projection chain), then WoutT
    bz_kernel<<<512, 256, 0, g_s1>>>(z, Wb, bb);
    cudaEventRecord(g_evBz, g_s1);
    WoutT_kernel<<<dim3(1024 / 32, KCAT / 32), dim3(32, 8), 0, g_s1>>>(Wout);
    cudaEventRecord(g_evWo, g_s1);

    // s2: weight prep (parallel with conv_hl on main)
    packWT_kernel<<<dim3(NPROJ / 32, CS / 32), dim3(32, 8), 0, g_s2>>>(Wq, Wkv, Wqp, Wkvp);
    packbias_kernel<<<(NPROJ + 255) / 256, 256, 0, g_s2>>>(bq, bkv, bqp, bkvp);
    cudaEventRecord(g_evPrep, g_s2);

    // main chain: s conversion -> proj -> pts
    conv_hl_kernel<<<(NN * CS + 255) / 256, 256>>>(s, pSh, pSl, NN * CS);
    cudaStreamWaitEvent(0, g_evPrep, 0);
    hgemm<true><<<dim3(NPROJ / 64, NN / 64), 256>>>(pSh, pSl, pWth, pWtl, pBias, pProj,
                                                    NN, CS, NPROJ, 0, 0, 0);
    pts_kernel<<<512, 384>>>(rot, trans);

    // logits needs bz output
    cudaStreamWaitEvent(0, g_evBz, 0);
    logits_softmax_kernel<<<dim3(64, 12), 256>>>(mask, head_w);
    cudaEventRecord(g_evLS, 0);

    // s2: opair (z-bound) concurrent with attn GEMM + assemble
    cudaStreamWaitEvent(g_s2, g_evLS, 0);
    opair_kernel<<<512, 256, 0, g_s2>>>(z);
    cudaEventRecord(g_evOp, g_s2);

    // main: attention output on tensor cores + assemble
    hgemm<false><<<dim3(1, NN / 64, Hh), 256>>>(pAh, pAl, pVTh, pVTl, nullptr, pO1,
                                                NN, NN, 64,
                                                (long)NN * NN / 2, (long)64 * NN / 2,
                                                (long)NN * 64);
    assemble_kernel<<<512, 192>>>(rot, trans);

    // join everything, then final GEMM
    cudaStreamWaitEvent(0, g_evOp, 0);
    cudaStreamWaitEvent(0, g_evWo, 0);
    hgemm<true><<<dim3(1024 / 64, NN / 64), 256>>>(pCath, pCatl, pWoTh, pWoTl, bout, out,
                                                   NN, KCAT, 1024, 0, 0, 0);
}